// round 1
// baseline (speedup 1.0000x reference)
#include <cuda_runtime.h>
#include <math.h>

#define Hh 64
#define Ww 64
#define MAXB 8
#define MAXP 512
#define MAXF 512
#define RECF 40          // floats per face record
#define EPSd 1e-10f
#define KEXP 142.85714285714286f   // MULT*MULT/DELTA
#define EXPANDc 0.02f

// scratch (device globals; no allocation allowed)
__device__ float g_vert[MAXB * MAXP * 8];          // pcx,pcy,pcz,xyx,xyy,pad,pad,pad
__device__ float g_face[MAXB * MAXF * RECF];       // face records

// ---------------- Kernel 1: vertex transform ----------------
__global__ void vert_kernel(const float* __restrict__ verts,
                            const float* __restrict__ rot,
                            const float* __restrict__ pos,
                            const float* __restrict__ proj,
                            int B, int P)
{
    int idx = blockIdx.x * blockDim.x + threadIdx.x;
    if (idx >= B * P) return;
    int b = idx / P;
    const float* v = verts + (size_t)idx * 3;
    const float* R = rot + (size_t)b * 9;
    const float* ps = pos + (size_t)b * 3;
    float d0 = v[0] - ps[0], d1 = v[1] - ps[1], d2 = v[2] - ps[2];
    float pcx = R[0]*d0 + R[1]*d1 + R[2]*d2;
    float pcy = R[3]*d0 + R[4]*d1 + R[5]*d2;
    float pcz = R[6]*d0 + R[7]*d1 + R[8]*d2;
    float x3 = pcx * proj[0];
    float y3 = pcy * proj[1];
    float z3 = pcz * proj[2];
    float xyx = x3 / z3;
    float xyy = y3 / z3;
    float* o = g_vert + (size_t)idx * 8;
    o[0] = pcx; o[1] = pcy; o[2] = pcz; o[3] = xyx; o[4] = xyy;
}

// ---------------- Kernel 2: face record build ----------------
__global__ void face_kernel(const int* __restrict__ faces,
                            const float* __restrict__ colors,
                            float* __restrict__ out_normal1,
                            int B, int P, int F)
{
    int idx = blockIdx.x * blockDim.x + threadIdx.x;
    if (idx >= B * F) return;
    int b = idx / F;
    const int* fi = faces + (size_t)idx * 3;
    int i0 = fi[0], i1 = fi[1], i2 = fi[2];
    const float* v0 = g_vert + ((size_t)b * P + i0) * 8;
    const float* v1 = g_vert + ((size_t)b * P + i1) * 8;
    const float* v2 = g_vert + ((size_t)b * P + i2) * 8;

    float ax = v0[3], ay = v0[4];
    float bx = v1[3], by = v1[4];
    float cx = v2[3], cy = v2[4];

    // normal from 3D tri
    float e1x = v1[0]-v0[0], e1y = v1[1]-v0[1], e1z = v1[2]-v0[2];
    float e2x = v2[0]-v0[0], e2y = v2[1]-v0[1], e2z = v2[2]-v0[2];
    float nx = e1y*e2z - e1z*e2y;
    float ny = e1z*e2x - e1x*e2z;
    float nz = e1x*e2y - e1y*e2x;
    float nrm = sqrtf(nx*nx + ny*ny + nz*nz) + 1e-12f;
    float* on = out_normal1 + (size_t)idx * 3;
    on[0] = nx / nrm; on[1] = ny / nrm; on[2] = nz / nrm;

    float det = (by - cy)*(ax - cx) + (cx - bx)*(ay - cy);
    float adet = fabsf(det);
    float det_safe = (adet < EPSd) ? EPSd : det;
    float invdet = 1.0f / det_safe;
    float validf = ((nz > 0.0f) && (adet > EPSd)) ? 1.0f : 0.0f;

    float A0 = by - cy, B0 = cx - bx;
    float A1 = cy - ay, B1 = ax - cx;

    float xmin = fminf(fminf(ax, bx), cx) - EXPANDc;
    float xmax = fmaxf(fmaxf(ax, bx), cx) + EXPANDc;
    float ymin = fminf(fminf(ay, by), cy) - EXPANDc;
    float ymax = fmaxf(fmaxf(ay, by), cy) + EXPANDc;

    float* R = g_face + (size_t)idx * RECF;
    R[0] = A0; R[1] = B0; R[2] = A1; R[3] = B1;
    R[4] = cx; R[5] = cy; R[6] = invdet; R[7] = v0[2];   // z0
    R[8] = v1[2]; R[9] = v2[2]; R[10] = validf; R[11] = xmin;
    R[12] = xmax; R[13] = ymin; R[14] = ymax;

    // segments: (a->b), (b->c), (c->a): px,py,vx,vy,inv
    float s[15];
    float pxs[3] = {ax, bx, cx}, pys[3] = {ay, by, cy};
    float qxs[3] = {bx, cx, ax}, qys[3] = {by, cy, ay};
    #pragma unroll
    for (int sI = 0; sI < 3; ++sI) {
        float vx = qxs[sI] - pxs[sI];
        float vy = qys[sI] - pys[sI];
        float inv = 1.0f / (vx*vx + vy*vy + 1e-12f);
        s[sI*5+0] = pxs[sI]; s[sI*5+1] = pys[sI];
        s[sI*5+2] = vx; s[sI*5+3] = vy; s[sI*5+4] = inv;
    }
    #pragma unroll
    for (int k = 0; k < 15; ++k) R[15 + k] = s[k];

    const float* cA = colors + ((size_t)b * P + i0) * 3;
    const float* cB = colors + ((size_t)b * P + i1) * 3;
    const float* cC = colors + ((size_t)b * P + i2) * 3;
    R[30] = cA[0]; R[31] = cA[1]; R[32] = cA[2];
    R[33] = cB[0]; R[34] = cB[1]; R[35] = cB[2];
    R[36] = cC[0]; R[37] = cC[1]; R[38] = cC[2];
    R[39] = 0.0f;
}

// ---------------- Kernel 3: pixel loop ----------------
__global__ void __launch_bounds__(256, 1)
pixel_kernel(float* __restrict__ out, int B, int F,
             int offP, int offH)
{
    extern __shared__ float sface[];   // F * RECF floats
    int b = blockIdx.y;

    // stage face records into shared (float4, coalesced)
    {
        const float4* src = (const float4*)(g_face + (size_t)b * F * RECF);
        float4* dst = (float4*)sface;
        int n4 = F * RECF / 4;
        for (int i = threadIdx.x; i < n4; i += blockDim.x)
            dst[i] = src[i];
    }
    __syncthreads();

    // pixel mapping: 16x16 tile per CTA, 8x4 tile per warp
    int tid = threadIdx.x;
    int lane = tid & 31;
    int warp = tid >> 5;
    int lx = lane & 7, ly = lane >> 3;         // 8x4
    int wx = warp & 1, wy = warp >> 1;         // 2x4 warps
    int xl = wx * 8 + lx;                      // 0..15
    int yl = wy * 4 + ly;                      // 0..15
    int tx = blockIdx.x & 3, ty = blockIdx.x >> 2;
    int x = tx * 16 + xl;
    int y = ty * 16 + yl;

    float px = (2.0f * (float)x + 1.0f - (float)Ww) / (float)Ww;
    float py = ((float)Hh - 2.0f * (float)y - 1.0f) / (float)Hh;

    float prod = 1.0f;
    float bestz = -1e30f;
    float bw0 = 0.0f, bw1 = 0.0f;
    int best = -1;

    for (int f = 0; f < F; ++f) {
        const float* R = &sface[f * RECF];
        float4 q0 = *(const float4*)(R + 0);   // A0,B0,A1,B1
        float4 q1 = *(const float4*)(R + 4);   // cx,cy,invdet,z0
        float4 q2 = *(const float4*)(R + 8);   // z1,z2,validf,xmin
        float4 q3 = *(const float4*)(R + 12);  // xmax,ymin,ymax,s0px

        float dx = px - q1.x;
        float dy = py - q1.y;
        float w0 = (q0.x * dx + q0.y * dy) * q1.z;
        float w1 = (q0.z * dx + q0.w * dy) * q1.z;
        float w2 = 1.0f - w0 - w1;
        bool covered = (w0 >= 0.0f) && (w1 >= 0.0f) && (w2 >= 0.0f);

        float z = w0 * q1.w + w1 * q2.x + w2 * q2.y;
        if (covered && (q2.z > 0.5f) && (z > bestz)) {
            bestz = z; bw0 = w0; bw1 = w1; best = f;
        }

        bool inb = (px >= q2.w) && (px <= q3.x) && (py >= q3.y) && (py <= q3.z);
        if (inb) {
            if (covered) {
                prod = 0.0f;
            } else {
                float4 sA = *(const float4*)(R + 16); // s0py,s0vx,s0vy,s0inv
                float4 sB = *(const float4*)(R + 20); // s1px,s1py,s1vx,s1vy
                float4 sC = *(const float4*)(R + 24); // s1inv,s2px,s2py,s2vx
                float2 sD = *(const float2*)(R + 28); // s2vy,s2inv

                // seg 0: p=(q3.w, sA.x) v=(sA.y,sA.z) inv=sA.w
                float rx = px - q3.w, ry = py - sA.x;
                float t0 = (rx * sA.y + ry * sA.z) * sA.w;
                t0 = fminf(fmaxf(t0, 0.0f), 1.0f);
                float ex = rx - t0 * sA.y, ey = ry - t0 * sA.z;
                float d2a = ex * ex + ey * ey;

                // seg 1: p=(sB.x,sB.y) v=(sB.z,sB.w) inv=sC.x
                rx = px - sB.x; ry = py - sB.y;
                float t1 = (rx * sB.z + ry * sB.w) * sC.x;
                t1 = fminf(fmaxf(t1, 0.0f), 1.0f);
                ex = rx - t1 * sB.z; ey = ry - t1 * sB.w;
                float d2b = ex * ex + ey * ey;

                // seg 2: p=(sC.y,sC.z) v=(sC.w,sD.x) inv=sD.y
                rx = px - sC.y; ry = py - sC.z;
                float t2 = (rx * sC.w + ry * sD.x) * sD.y;
                t2 = fminf(fmaxf(t2, 0.0f), 1.0f);
                ex = rx - t2 * sC.w; ey = ry - t2 * sD.x;
                float d2c = ex * ex + ey * ey;

                float d2 = fminf(fminf(d2a, d2b), d2c);
                float contrib = __expf(-d2 * KEXP);
                prod *= (1.0f - contrib);
            }
        }
    }

    float r_, g_, bl_, hm;
    if (best >= 0) {
        const float* C = &sface[best * RECF + 30];
        float w2b = 1.0f - bw0 - bw1;
        r_  = bw0 * C[0] + bw1 * C[3] + w2b * C[6];
        g_  = bw0 * C[1] + bw1 * C[4] + w2b * C[7];
        bl_ = bw0 * C[2] + bw1 * C[5] + w2b * C[8];
        hm  = bw0 + bw1 + w2b;
    } else {
        r_ = g_ = bl_ = 0.0f; hm = 0.0f;
    }

    int pix = (b * Hh + y) * Ww + x;
    float* rgb = out + (size_t)pix * 3;
    rgb[0] = r_; rgb[1] = g_; rgb[2] = bl_;
    out[offP + pix] = 1.0f - prod;
    out[offH + pix] = hm;
}

extern "C" void kernel_launch(void* const* d_in, const int* in_sizes, int n_in,
                              void* d_out, int out_size)
{
    const float* verts  = (const float*)d_in[0];
    const int*   faces  = (const int*)d_in[1];
    const float* rot    = (const float*)d_in[2];
    const float* pos    = (const float*)d_in[3];
    const float* proj   = (const float*)d_in[4];
    const float* colors = (const float*)d_in[5];
    float* out = (float*)d_out;

    int B = in_sizes[3] / 3;
    int P = in_sizes[0] / (3 * B);
    int F = in_sizes[1] / (3 * B);

    int offP = B * Hh * Ww * 3;              // improb
    int offN = offP + B * Hh * Ww;           // normal1
    int offH = offN + B * F * 3;             // hardmask

    int nv = B * P;
    vert_kernel<<<(nv + 255) / 256, 256>>>(verts, rot, pos, proj, B, P);

    int nf = B * F;
    face_kernel<<<(nf + 255) / 256, 256>>>(faces, colors, out + offN, B, P, F);

    int smem = F * RECF * (int)sizeof(float);   // 80 KB
    cudaFuncSetAttribute(pixel_kernel, cudaFuncAttributeMaxDynamicSharedMemorySize, smem);
    dim3 grid(16, B);
    pixel_kernel<<<grid, 256, smem>>>(out, B, F, offP, offH);
}

// round 2
// speedup vs baseline: 1.5640x; 1.5640x over previous
#include <cuda_runtime.h>
#include <math.h>

#define Hh 64
#define Ww 64
#define MAXB 8
#define MAXP 512
#define MAXF 512
#define RECF 40
#define NCHUNK 4
#define EPSd 1e-10f
#define KEXP 142.85714285714286f   // MULT*MULT/DELTA
#define EXPANDc 0.02f
#define NPIX (Hh * Ww)

// scratch (device globals; no allocation allowed)
__device__ float  g_face[MAXB * MAXF * RECF];
__device__ float4 g_partA[MAXB * NCHUNK * NPIX];   // bestz, bw0, bw1, bestf(as float)
__device__ float  g_partP[MAXB * NCHUNK * NPIX];   // prod

// ---------------- Kernel 1: fused vertex transform + face record build ----------------
__global__ void __launch_bounds__(512)
geom_kernel(const float* __restrict__ verts,
            const int* __restrict__ faces,
            const float* __restrict__ rot,
            const float* __restrict__ pos,
            const float* __restrict__ proj,
            const float* __restrict__ colors,
            float* __restrict__ out_normal1,
            int B, int P, int F)
{
    __shared__ float sv[MAXP * 5];   // pcx,pcy,pcz,xyx,xyy
    int b = blockIdx.x;

    float R0 = rot[b*9+0], R1 = rot[b*9+1], R2 = rot[b*9+2];
    float R3 = rot[b*9+3], R4 = rot[b*9+4], R5 = rot[b*9+5];
    float R6 = rot[b*9+6], R7 = rot[b*9+7], R8 = rot[b*9+8];
    float p0 = pos[b*3+0], p1 = pos[b*3+1], p2 = pos[b*3+2];
    float pr0 = proj[0], pr1 = proj[1], pr2 = proj[2];

    for (int i = threadIdx.x; i < P; i += blockDim.x) {
        const float* v = verts + ((size_t)(b * P + i)) * 3;
        float d0 = v[0] - p0, d1 = v[1] - p1, d2 = v[2] - p2;
        float pcx = R0*d0 + R1*d1 + R2*d2;
        float pcy = R3*d0 + R4*d1 + R5*d2;
        float pcz = R6*d0 + R7*d1 + R8*d2;
        float z3 = pcz * pr2;
        sv[i*5+0] = pcx; sv[i*5+1] = pcy; sv[i*5+2] = pcz;
        sv[i*5+3] = (pcx * pr0) / z3;
        sv[i*5+4] = (pcy * pr1) / z3;
    }
    __syncthreads();

    for (int i = threadIdx.x; i < F; i += blockDim.x) {
        const int* fi = faces + ((size_t)(b * F + i)) * 3;
        int i0 = fi[0], i1 = fi[1], i2 = fi[2];
        const float* v0 = sv + i0 * 5;
        const float* v1 = sv + i1 * 5;
        const float* v2 = sv + i2 * 5;

        float ax = v0[3], ay = v0[4];
        float bx = v1[3], by = v1[4];
        float cx = v2[3], cy = v2[4];

        float e1x = v1[0]-v0[0], e1y = v1[1]-v0[1], e1z = v1[2]-v0[2];
        float e2x = v2[0]-v0[0], e2y = v2[1]-v0[1], e2z = v2[2]-v0[2];
        float nx = e1y*e2z - e1z*e2y;
        float ny = e1z*e2x - e1x*e2z;
        float nz = e1x*e2y - e1y*e2x;
        float nrm = sqrtf(nx*nx + ny*ny + nz*nz) + 1e-12f;
        float* on = out_normal1 + ((size_t)(b * F + i)) * 3;
        on[0] = nx / nrm; on[1] = ny / nrm; on[2] = nz / nrm;

        float det = (by - cy)*(ax - cx) + (cx - bx)*(ay - cy);
        float adet = fabsf(det);
        float det_safe = (adet < EPSd) ? EPSd : det;
        float invdet = 1.0f / det_safe;
        float validf = ((nz > 0.0f) && (adet > EPSd)) ? 1.0f : 0.0f;

        float xmin = fminf(fminf(ax, bx), cx) - EXPANDc;
        float xmax = fmaxf(fmaxf(ax, bx), cx) + EXPANDc;
        float ymin = fminf(fminf(ay, by), cy) - EXPANDc;
        float ymax = fmaxf(fmaxf(ay, by), cy) + EXPANDc;

        float* R = g_face + ((size_t)(b * F + i)) * RECF;
        R[0] = by - cy; R[1] = cx - bx; R[2] = cy - ay; R[3] = ax - cx;
        R[4] = cx; R[5] = cy; R[6] = invdet; R[7] = v0[2];
        R[8] = v1[2]; R[9] = v2[2]; R[10] = validf; R[11] = xmin;
        R[12] = xmax; R[13] = ymin; R[14] = ymax;

        float pxs[3] = {ax, bx, cx}, pys[3] = {ay, by, cy};
        float qxs[3] = {bx, cx, ax}, qys[3] = {by, cy, ay};
        #pragma unroll
        for (int sI = 0; sI < 3; ++sI) {
            float vx = qxs[sI] - pxs[sI];
            float vy = qys[sI] - pys[sI];
            float inv = 1.0f / (vx*vx + vy*vy + 1e-12f);
            R[15 + sI*5 + 0] = pxs[sI]; R[15 + sI*5 + 1] = pys[sI];
            R[15 + sI*5 + 2] = vx; R[15 + sI*5 + 3] = vy; R[15 + sI*5 + 4] = inv;
        }

        const float* cA = colors + ((size_t)(b * P + i0)) * 3;
        const float* cB = colors + ((size_t)(b * P + i1)) * 3;
        const float* cC = colors + ((size_t)(b * P + i2)) * 3;
        R[30] = cA[0]; R[31] = cA[1]; R[32] = cA[2];
        R[33] = cB[0]; R[34] = cB[1]; R[35] = cB[2];
        R[36] = cC[0]; R[37] = cC[1]; R[38] = cC[2];
        R[39] = 0.0f;
    }
}

// ---------------- Kernel 2: pixel loop (tile-culled, face-chunked) ----------------
__global__ void __launch_bounds__(256)
pixel_kernel(int B, int F)
{
    extern __shared__ float sface[];     // FPC * RECF floats
    __shared__ int wcnt[8];

    int b = blockIdx.z, chunk = blockIdx.y, tile = blockIdx.x;
    int FPC = F / NCHUNK;
    int tid = threadIdx.x;
    int tx = tile & 3, ty = tile >> 2;

    // NDC extents of this 16x16 pixel tile
    float txlo = (2.0f * (float)(tx*16)      + 1.0f - (float)Ww) / (float)Ww;
    float txhi = (2.0f * (float)(tx*16 + 15) + 1.0f - (float)Ww) / (float)Ww;
    float tyhi = ((float)Hh - 2.0f * (float)(ty*16)      - 1.0f) / (float)Hh;
    float tylo = ((float)Hh - 2.0f * (float)(ty*16 + 15) - 1.0f) / (float)Hh;

    // ---- order-preserving face culling + compaction ----
    bool acc = false;
    int fg = 0;
    const float* Rg = nullptr;
    if (tid < FPC) {
        fg = chunk * FPC + tid;
        Rg = g_face + ((size_t)(b * F + fg)) * RECF;
        float xmin = Rg[11], xmax = Rg[12], ymin = Rg[13], ymax = Rg[14];
        acc = (xmin <= txhi) && (xmax >= txlo) && (ymin <= tyhi) && (ymax >= tylo);
    }
    unsigned m = __ballot_sync(0xffffffffu, acc);
    int lane = tid & 31, wid = tid >> 5;
    if (lane == 0) wcnt[wid] = __popc(m);
    __syncthreads();
    int base = 0, nf = 0;
    #pragma unroll
    for (int w = 0; w < 8; ++w) {
        int c = wcnt[w];
        if (w < wid) base += c;
        nf += c;
    }
    if (acc) {
        int slot = base + __popc(m & ((1u << lane) - 1u));
        float4* d = (float4*)(sface + slot * RECF);
        const float4* s = (const float4*)Rg;
        #pragma unroll
        for (int k = 0; k < 10; ++k) d[k] = s[k];
        sface[slot * RECF + 39] = (float)fg;
    }
    __syncthreads();

    // ---- pixel mapping: 16x16 tile per CTA, 8x4 per warp ----
    int lx = lane & 7, ly = lane >> 3;
    int wx = wid & 1, wy = wid >> 1;
    int x = tx * 16 + wx * 8 + lx;
    int y = ty * 16 + wy * 4 + ly;

    float px = (2.0f * (float)x + 1.0f - (float)Ww) / (float)Ww;
    float py = ((float)Hh - 2.0f * (float)y - 1.0f) / (float)Hh;

    float prod = 1.0f;
    float bestz = -1e30f;
    float bw0 = 0.0f, bw1 = 0.0f;
    int bestslot = -1;

    for (int f = 0; f < nf; ++f) {
        const float* R = &sface[f * RECF];
        float4 q0 = *(const float4*)(R + 0);
        float4 q1 = *(const float4*)(R + 4);
        float4 q2 = *(const float4*)(R + 8);
        float4 q3 = *(const float4*)(R + 12);

        float dx = px - q1.x;
        float dy = py - q1.y;
        float w0 = (q0.x * dx + q0.y * dy) * q1.z;
        float w1 = (q0.z * dx + q0.w * dy) * q1.z;
        float w2 = 1.0f - w0 - w1;
        bool covered = (w0 >= 0.0f) && (w1 >= 0.0f) && (w2 >= 0.0f);

        float z = w0 * q1.w + w1 * q2.x + w2 * q2.y;
        if (covered && (q2.z > 0.5f) && (z > bestz)) {
            bestz = z; bw0 = w0; bw1 = w1; bestslot = f;
        }

        bool inb = (px >= q2.w) && (px <= q3.x) && (py >= q3.y) && (py <= q3.z);
        if (inb) {
            if (covered) {
                prod = 0.0f;
            } else {
                float4 sA = *(const float4*)(R + 16);
                float4 sB = *(const float4*)(R + 20);
                float4 sC = *(const float4*)(R + 24);
                float2 sD = *(const float2*)(R + 28);

                float rx = px - q3.w, ry = py - sA.x;
                float t0 = (rx * sA.y + ry * sA.z) * sA.w;
                t0 = fminf(fmaxf(t0, 0.0f), 1.0f);
                float ex = rx - t0 * sA.y, ey = ry - t0 * sA.z;
                float d2a = ex * ex + ey * ey;

                rx = px - sB.x; ry = py - sB.y;
                float t1 = (rx * sB.z + ry * sB.w) * sC.x;
                t1 = fminf(fmaxf(t1, 0.0f), 1.0f);
                ex = rx - t1 * sB.z; ey = ry - t1 * sB.w;
                float d2b = ex * ex + ey * ey;

                rx = px - sC.y; ry = py - sC.z;
                float t2 = (rx * sC.w + ry * sD.x) * sD.y;
                t2 = fminf(fmaxf(t2, 0.0f), 1.0f);
                ex = rx - t2 * sC.w; ey = ry - t2 * sD.x;
                float d2c = ex * ex + ey * ey;

                float d2 = fminf(fminf(d2a, d2b), d2c);
                float contrib = __expf(-d2 * KEXP);
                prod *= (1.0f - contrib);
            }
        }
    }

    float bf = (bestslot >= 0) ? sface[bestslot * RECF + 39] : -1.0f;
    int pix = y * Ww + x;
    int o = (b * NCHUNK + chunk) * NPIX + pix;
    g_partA[o] = make_float4(bestz, bw0, bw1, bf);
    g_partP[o] = prod;
}

// ---------------- Kernel 3: combine chunk partials ----------------
__global__ void __launch_bounds__(256)
combine_kernel(float* __restrict__ out, int B, int F, int offP, int offH)
{
    int idx = blockIdx.x * blockDim.x + threadIdx.x;
    if (idx >= B * NPIX) return;
    int b = idx / NPIX;
    int p = idx - b * NPIX;

    float Z = -1e38f, b0 = 0.0f, b1 = 0.0f, bf = -1.0f;
    float prod = 1.0f;
    #pragma unroll
    for (int c = 0; c < NCHUNK; ++c) {
        int o = (b * NCHUNK + c) * NPIX + p;
        float4 a = g_partA[o];
        prod *= g_partP[o];
        if (a.x > Z) { Z = a.x; b0 = a.y; b1 = a.z; bf = a.w; }
    }

    float r = 0.0f, g = 0.0f, bl = 0.0f, hm = 0.0f;
    if (bf >= 0.0f) {
        const float* C = g_face + ((size_t)(b * F) + (int)bf) * RECF + 30;
        float w2 = 1.0f - b0 - b1;
        r  = b0 * C[0] + b1 * C[3] + w2 * C[6];
        g  = b0 * C[1] + b1 * C[4] + w2 * C[7];
        bl = b0 * C[2] + b1 * C[5] + w2 * C[8];
        hm = b0 + b1 + w2;
    }

    float* rgb = out + (size_t)idx * 3;
    rgb[0] = r; rgb[1] = g; rgb[2] = bl;
    out[offP + idx] = 1.0f - prod;
    out[offH + idx] = hm;
}

extern "C" void kernel_launch(void* const* d_in, const int* in_sizes, int n_in,
                              void* d_out, int out_size)
{
    const float* verts  = (const float*)d_in[0];
    const int*   faces  = (const int*)d_in[1];
    const float* rot    = (const float*)d_in[2];
    const float* pos    = (const float*)d_in[3];
    const float* proj   = (const float*)d_in[4];
    const float* colors = (const float*)d_in[5];
    float* out = (float*)d_out;

    int B = in_sizes[3] / 3;
    int P = in_sizes[0] / (3 * B);
    int F = in_sizes[1] / (3 * B);

    int offP = B * NPIX * 3;        // improb
    int offN = offP + B * NPIX;     // normal1
    int offH = offN + B * F * 3;    // hardmask

    geom_kernel<<<B, 512>>>(verts, faces, rot, pos, proj, colors, out + offN, B, P, F);

    int FPC = F / NCHUNK;
    dim3 gridB(16, NCHUNK, B);
    pixel_kernel<<<gridB, 256, FPC * RECF * (int)sizeof(float)>>>(B, F);

    int npx = B * NPIX;
    combine_kernel<<<(npx + 255) / 256, 256>>>(out, B, F, offP, offH);
}

// round 3
// speedup vs baseline: 2.1429x; 1.3701x over previous
#include <cuda_runtime.h>
#include <math.h>

#define Hh 64
#define Ww 64
#define MAXB 8
#define MAXP 512
#define MAXF 512
#define RECF 40
#define NCHUNK 4
#define FPCmax 128
#define EPSd 1e-10f
#define KEXP 142.85714285714286f   // MULT*MULT/DELTA
#define EXPANDc 0.02f
#define NPIX (Hh * Ww)

// scratch (device globals; no allocation allowed)
__device__ float4 g_partA[MAXB * NCHUNK * NPIX];   // bestz, bw0, bw1, bestf(as float)
__device__ float  g_partP[MAXB * NCHUNK * NPIX];   // prod
__device__ int    g_cnt[MAXB * 16];                // per (b,tile) arrival counter (stays 0 between replays)

__global__ void __launch_bounds__(256)
render_kernel(const float* __restrict__ verts,
              const int* __restrict__ faces,
              const float* __restrict__ rot,
              const float* __restrict__ pos,
              const float* __restrict__ proj,
              const float* __restrict__ colors,
              float* __restrict__ out,
              int B, int P, int F,
              int offP, int offN, int offH)
{
    __shared__ float sv[MAXP * 5];            // pcx,pcy,pcz,xyx,xyy
    __shared__ float sface[FPCmax * RECF];    // compacted face records
    __shared__ int wcnt[8];
    __shared__ int sh_old;

    int b = blockIdx.z, chunk = blockIdx.y, tile = blockIdx.x;
    int FPC = F / NCHUNK;
    int tid = threadIdx.x;
    int lane = tid & 31, wid = tid >> 5;
    int tx = tile & 3, ty = tile >> 2;

    // ---- stage per-batch camera ----
    float R0 = rot[b*9+0], R1 = rot[b*9+1], R2 = rot[b*9+2];
    float R3 = rot[b*9+3], R4 = rot[b*9+4], R5 = rot[b*9+5];
    float R6 = rot[b*9+6], R7 = rot[b*9+7], R8 = rot[b*9+8];
    float p0 = pos[b*3+0], p1 = pos[b*3+1], p2 = pos[b*3+2];
    float pr0 = proj[0], pr1 = proj[1], pr2 = proj[2];

    // ---- vertex transform into smem ----
    for (int i = tid; i < P; i += blockDim.x) {
        const float* v = verts + ((size_t)(b * P + i)) * 3;
        float d0 = v[0] - p0, d1 = v[1] - p1, d2 = v[2] - p2;
        float pcx = R0*d0 + R1*d1 + R2*d2;
        float pcy = R3*d0 + R4*d1 + R5*d2;
        float pcz = R6*d0 + R7*d1 + R8*d2;
        float z3 = pcz * pr2;
        sv[i*5+0] = pcx; sv[i*5+1] = pcy; sv[i*5+2] = pcz;
        sv[i*5+3] = (pcx * pr0) / z3;
        sv[i*5+4] = (pcy * pr1) / z3;
    }
    __syncthreads();

    // ---- NDC extents of this 16x16 pixel tile ----
    float txlo = (2.0f * (float)(tx*16)      + 1.0f - (float)Ww) / (float)Ww;
    float txhi = (2.0f * (float)(tx*16 + 15) + 1.0f - (float)Ww) / (float)Ww;
    float tyhi = ((float)Hh - 2.0f * (float)(ty*16)      - 1.0f) / (float)Hh;
    float tylo = ((float)Hh - 2.0f * (float)(ty*16 + 15) - 1.0f) / (float)Hh;

    // ---- per-face: normal (+ optional output), bbox, cull test ----
    bool acc = false;
    int i0 = 0, i1 = 0, i2 = 0, fg = 0;
    float ax=0, ay=0, bx=0, by=0, cx=0, cy=0;
    float nz = 0, xmin=0, xmax=0, ymin=0, ymax=0;
    if (tid < FPC) {
        fg = chunk * FPC + tid;
        const int* fi = faces + ((size_t)(b * F + fg)) * 3;
        i0 = fi[0]; i1 = fi[1]; i2 = fi[2];
        const float* v0 = sv + i0 * 5;
        const float* v1 = sv + i1 * 5;
        const float* v2 = sv + i2 * 5;
        ax = v0[3]; ay = v0[4];
        bx = v1[3]; by = v1[4];
        cx = v2[3]; cy = v2[4];

        float e1x = v1[0]-v0[0], e1y = v1[1]-v0[1], e1z = v1[2]-v0[2];
        float e2x = v2[0]-v0[0], e2y = v2[1]-v0[1], e2z = v2[2]-v0[2];
        float nx = e1y*e2z - e1z*e2y;
        float ny = e1z*e2x - e1x*e2z;
        nz = e1x*e2y - e1y*e2x;
        if (tile == 0) {
            float nrm = sqrtf(nx*nx + ny*ny + nz*nz) + 1e-12f;
            float* on = out + offN + ((size_t)(b * F + fg)) * 3;
            on[0] = nx / nrm; on[1] = ny / nrm; on[2] = nz / nrm;
        }

        xmin = fminf(fminf(ax, bx), cx) - EXPANDc;
        xmax = fmaxf(fmaxf(ax, bx), cx) + EXPANDc;
        ymin = fminf(fminf(ay, by), cy) - EXPANDc;
        ymax = fmaxf(fmaxf(ay, by), cy) + EXPANDc;
        acc = (xmin <= txhi) && (xmax >= txlo) && (ymin <= tyhi) && (ymax >= tylo);
    }

    // ---- order-preserving compaction ----
    unsigned m = __ballot_sync(0xffffffffu, acc);
    if (lane == 0) wcnt[wid] = __popc(m);
    __syncthreads();
    int base = 0, nf = 0;
    #pragma unroll
    for (int w = 0; w < 8; ++w) {
        int c = wcnt[w];
        if (w < wid) base += c;
        nf += c;
    }

    // ---- build full record only for accepted faces ----
    if (acc) {
        int slot = base + __popc(m & ((1u << lane) - 1u));
        float* Rr = sface + slot * RECF;

        float det = (by - cy)*(ax - cx) + (cx - bx)*(ay - cy);
        float adet = fabsf(det);
        float det_safe = (adet < EPSd) ? EPSd : det;
        float invdet = 1.0f / det_safe;
        float validf = ((nz > 0.0f) && (adet > EPSd)) ? 1.0f : 0.0f;

        Rr[0] = by - cy; Rr[1] = cx - bx; Rr[2] = cy - ay; Rr[3] = ax - cx;
        Rr[4] = cx; Rr[5] = cy; Rr[6] = invdet;
        Rr[7] = sv[i0*5+2]; Rr[8] = sv[i1*5+2]; Rr[9] = sv[i2*5+2];
        Rr[10] = validf; Rr[11] = xmin; Rr[12] = xmax; Rr[13] = ymin; Rr[14] = ymax;

        float pxs[3] = {ax, bx, cx}, pys[3] = {ay, by, cy};
        float qxs[3] = {bx, cx, ax}, qys[3] = {by, cy, ay};
        #pragma unroll
        for (int sI = 0; sI < 3; ++sI) {
            float vx = qxs[sI] - pxs[sI];
            float vy = qys[sI] - pys[sI];
            float inv = 1.0f / (vx*vx + vy*vy + 1e-12f);
            Rr[15 + sI*5 + 0] = pxs[sI]; Rr[15 + sI*5 + 1] = pys[sI];
            Rr[15 + sI*5 + 2] = vx; Rr[15 + sI*5 + 3] = vy; Rr[15 + sI*5 + 4] = inv;
        }
        Rr[39] = (float)fg;
    }
    __syncthreads();

    // ---- pixel mapping: 16x16 tile, 8x4 per warp ----
    int lx = lane & 7, ly = lane >> 3;
    int wx = wid & 1, wy = wid >> 1;
    int x = tx * 16 + wx * 8 + lx;
    int y = ty * 16 + wy * 4 + ly;

    float px = (2.0f * (float)x + 1.0f - (float)Ww) / (float)Ww;
    float py = ((float)Hh - 2.0f * (float)y - 1.0f) / (float)Hh;

    float prod = 1.0f;
    float bestz = -1e30f;
    float bw0 = 0.0f, bw1 = 0.0f;
    int bestslot = -1;

    for (int f = 0; f < nf; ++f) {
        const float* Rr = &sface[f * RECF];
        float4 q0 = *(const float4*)(Rr + 0);
        float4 q1 = *(const float4*)(Rr + 4);
        float4 q2 = *(const float4*)(Rr + 8);
        float4 q3 = *(const float4*)(Rr + 12);

        float dx = px - q1.x;
        float dy = py - q1.y;
        float w0 = (q0.x * dx + q0.y * dy) * q1.z;
        float w1 = (q0.z * dx + q0.w * dy) * q1.z;
        float w2 = 1.0f - w0 - w1;
        bool covered = (w0 >= 0.0f) && (w1 >= 0.0f) && (w2 >= 0.0f);

        float z = w0 * q1.w + w1 * q2.x + w2 * q2.y;
        if (covered && (q2.z > 0.5f) && (z > bestz)) {
            bestz = z; bw0 = w0; bw1 = w1; bestslot = f;
        }

        bool inb = (px >= q2.w) && (px <= q3.x) && (py >= q3.y) && (py <= q3.z);
        if (inb) {
            if (covered) {
                prod = 0.0f;
            } else {
                float4 sA = *(const float4*)(Rr + 16);
                float4 sB = *(const float4*)(Rr + 20);
                float4 sC = *(const float4*)(Rr + 24);
                float2 sD = *(const float2*)(Rr + 28);

                float rx = px - q3.w, ry = py - sA.x;
                float t0 = (rx * sA.y + ry * sA.z) * sA.w;
                t0 = fminf(fmaxf(t0, 0.0f), 1.0f);
                float ex = rx - t0 * sA.y, ey = ry - t0 * sA.z;
                float d2a = ex * ex + ey * ey;

                rx = px - sB.x; ry = py - sB.y;
                float t1 = (rx * sB.z + ry * sB.w) * sC.x;
                t1 = fminf(fmaxf(t1, 0.0f), 1.0f);
                ex = rx - t1 * sB.z; ey = ry - t1 * sB.w;
                float d2b = ex * ex + ey * ey;

                rx = px - sC.y; ry = py - sC.z;
                float t2 = (rx * sC.w + ry * sD.x) * sD.y;
                t2 = fminf(fmaxf(t2, 0.0f), 1.0f);
                ex = rx - t2 * sC.w; ey = ry - t2 * sD.x;
                float d2c = ex * ex + ey * ey;

                float d2 = fminf(fminf(d2a, d2b), d2c);
                float contrib = __expf(-d2 * KEXP);
                prod *= (1.0f - contrib);
            }
        }
    }

    float bf = (bestslot >= 0) ? sface[bestslot * RECF + 39] : -1.0f;
    int pix = y * Ww + x;
    int o = (b * NCHUNK + chunk) * NPIX + pix;
    __stcg(&g_partA[o], make_float4(bestz, bw0, bw1, bf));
    __stcg(&g_partP[o], prod);

    // ---- last-CTA-per-(b,tile) combines ----
    __threadfence();
    __syncthreads();
    if (tid == 0) sh_old = atomicAdd(&g_cnt[b * 16 + tile], 1);
    __syncthreads();
    if (sh_old != NCHUNK - 1) return;
    __threadfence();

    float Z = -1e38f, b0 = 0.0f, b1 = 0.0f, bff = -1.0f;
    float pacc = 1.0f;
    #pragma unroll
    for (int c = 0; c < NCHUNK; ++c) {
        int oo = (b * NCHUNK + c) * NPIX + pix;
        float4 a = __ldcg(&g_partA[oo]);
        pacc *= __ldcg(&g_partP[oo]);
        if (a.x > Z) { Z = a.x; b0 = a.y; b1 = a.z; bff = a.w; }
    }

    float r = 0.0f, g = 0.0f, bl = 0.0f, hm = 0.0f;
    if (bff >= 0.0f) {
        int fid = (int)bff;
        const int* fi = faces + ((size_t)(b * F + fid)) * 3;
        const float* cA = colors + ((size_t)(b * P + fi[0])) * 3;
        const float* cB = colors + ((size_t)(b * P + fi[1])) * 3;
        const float* cC = colors + ((size_t)(b * P + fi[2])) * 3;
        float w2 = 1.0f - b0 - b1;
        r  = b0 * cA[0] + b1 * cB[0] + w2 * cC[0];
        g  = b0 * cA[1] + b1 * cB[1] + w2 * cC[1];
        bl = b0 * cA[2] + b1 * cB[2] + w2 * cC[2];
        hm = b0 + b1 + w2;
    }

    int gidx = b * NPIX + pix;
    float* rgb = out + (size_t)gidx * 3;
    rgb[0] = r; rgb[1] = g; rgb[2] = bl;
    out[offP + gidx] = 1.0f - pacc;
    out[offH + gidx] = hm;

    if (tid == 0) atomicExch(&g_cnt[b * 16 + tile], 0);   // reset for next replay
}

extern "C" void kernel_launch(void* const* d_in, const int* in_sizes, int n_in,
                              void* d_out, int out_size)
{
    const float* verts  = (const float*)d_in[0];
    const int*   faces  = (const int*)d_in[1];
    const float* rot    = (const float*)d_in[2];
    const float* pos    = (const float*)d_in[3];
    const float* proj   = (const float*)d_in[4];
    const float* colors = (const float*)d_in[5];
    float* out = (float*)d_out;

    int B = in_sizes[3] / 3;
    int P = in_sizes[0] / (3 * B);
    int F = in_sizes[1] / (3 * B);

    int offP = B * NPIX * 3;        // improb
    int offN = offP + B * NPIX;     // normal1
    int offH = offN + B * F * 3;    // hardmask

    dim3 grid(16, NCHUNK, B);
    render_kernel<<<grid, 256>>>(verts, faces, rot, pos, proj, colors, out,
                                 B, P, F, offP, offN, offH);
}

// round 4
// speedup vs baseline: 2.7443x; 1.2807x over previous
#include <cuda_runtime.h>
#include <math.h>

#define Hh 64
#define Ww 64
#define MAXB 8
#define MAXP 512
#define MAXF 512
#define RECF 32
#define NCHUNK 8
#define FPCmax 64
#define EPSd 1e-10f
#define KEXP 142.85714285714286f   // MULT*MULT/DELTA
#define EXPANDc 0.02f
#define NPIX (Hh * Ww)

// scratch (device globals; no allocation allowed)
__device__ float4 g_partA[MAXB * NCHUNK * NPIX];   // bestz, bw0, bw1, bestfid(as float)
__device__ float  g_partP[MAXB * NCHUNK * NPIX];   // prod
__device__ int    g_cnt[MAXB * 16];                // per (b,tile) arrival counter

__global__ void __launch_bounds__(256)
render_kernel(const float* __restrict__ verts,
              const int* __restrict__ faces,
              const float* __restrict__ rot,
              const float* __restrict__ pos,
              const float* __restrict__ proj,
              const float* __restrict__ colors,
              float* __restrict__ out,
              int B, int P, int F,
              int offP, int offN, int offH)
{
    __shared__ float sface[FPCmax * RECF];   // 8 KB
    __shared__ int wcnt[8];
    __shared__ int sh_old;

    int b = blockIdx.z, chunk = blockIdx.y, tile = blockIdx.x;
    int FPC = F / NCHUNK;
    int tid = threadIdx.x;
    int lane = tid & 31, wid = tid >> 5;
    int tx = tile & 3, ty = tile >> 2;

    // NDC extents of this 16x16 pixel tile
    float txlo = (2.0f * (float)(tx*16)      + 1.0f - (float)Ww) / (float)Ww;
    float txhi = (2.0f * (float)(tx*16 + 15) + 1.0f - (float)Ww) / (float)Ww;
    float tyhi = ((float)Hh - 2.0f * (float)(ty*16)      - 1.0f) / (float)Hh;
    float tylo = ((float)Hh - 2.0f * (float)(ty*16 + 15) - 1.0f) / (float)Hh;

    // ---- per-face geometry (threads 0..FPC-1), direct vertex transform ----
    bool acc = false;
    int fg = 0;
    float ax=0, ay=0, bx=0, by=0, cx=0, cy=0;
    float z0=0, z1=0, z2s=0, nz=0;
    float xmin=0, xmax=0, ymin=0, ymax=0;
    bool validg = false;

    if (tid < FPC) {
        // camera constants (uniform per batch)
        float R0 = rot[b*9+0], R1 = rot[b*9+1], R2 = rot[b*9+2];
        float R3 = rot[b*9+3], R4 = rot[b*9+4], R5 = rot[b*9+5];
        float R6 = rot[b*9+6], R7 = rot[b*9+7], R8 = rot[b*9+8];
        float p0 = pos[b*3+0], p1 = pos[b*3+1], p2 = pos[b*3+2];
        float pr0 = proj[0], pr1 = proj[1], pr2 = proj[2];

        fg = chunk * FPC + tid;
        const int* fi = faces + ((size_t)(b * F + fg)) * 3;
        int idxs[3] = {fi[0], fi[1], fi[2]};
        float pcx[3], pcy[3], pcz[3], X[3], Y[3];
        #pragma unroll
        for (int k = 0; k < 3; ++k) {
            const float* v = verts + ((size_t)(b * P + idxs[k])) * 3;
            float d0 = v[0]-p0, d1 = v[1]-p1, d2 = v[2]-p2;
            pcx[k] = R0*d0 + R1*d1 + R2*d2;
            pcy[k] = R3*d0 + R4*d1 + R5*d2;
            pcz[k] = R6*d0 + R7*d1 + R8*d2;
            float zz = pcz[k] * pr2;
            X[k] = (pcx[k] * pr0) / zz;
            Y[k] = (pcy[k] * pr1) / zz;
        }
        float e1x = pcx[1]-pcx[0], e1y = pcy[1]-pcy[0], e1z = pcz[1]-pcz[0];
        float e2x = pcx[2]-pcx[0], e2y = pcy[2]-pcy[0], e2z = pcz[2]-pcz[0];
        float nx = e1y*e2z - e1z*e2y;
        float ny = e1z*e2x - e1x*e2z;
        nz = e1x*e2y - e1y*e2x;
        if (tile == 0) {
            float nrm = sqrtf(nx*nx + ny*ny + nz*nz) + 1e-12f;
            float* on = out + offN + ((size_t)(b * F + fg)) * 3;
            on[0] = nx / nrm; on[1] = ny / nrm; on[2] = nz / nrm;
        }
        ax = X[0]; ay = Y[0]; bx = X[1]; by = Y[1]; cx = X[2]; cy = Y[2];
        z0 = pcz[0]; z1 = pcz[1]; z2s = pcz[2];

        xmin = fminf(fminf(ax, bx), cx) - EXPANDc;
        xmax = fmaxf(fmaxf(ax, bx), cx) + EXPANDc;
        ymin = fminf(fminf(ay, by), cy) - EXPANDc;
        ymax = fmaxf(fmaxf(ay, by), cy) + EXPANDc;
        acc = (xmin <= txhi) && (xmax >= txlo) && (ymin <= tyhi) && (ymax >= tylo);
    }

    // ---- order-preserving compaction ----
    unsigned m = __ballot_sync(0xffffffffu, acc);
    if (lane == 0) wcnt[wid] = __popc(m);
    __syncthreads();
    int base = 0, nf = 0;
    #pragma unroll
    for (int w = 0; w < 8; ++w) {
        int c = wcnt[w];
        if (w < wid) base += c;
        nf += c;
    }

    if (acc) {
        int slot = base + __popc(m & ((1u << lane) - 1u));
        float* Rr = sface + slot * RECF;

        float det = (by - cy)*(ax - cx) + (cx - bx)*(ay - cy);
        float adet = fabsf(det);
        float det_safe = (adet < EPSd) ? EPSd : det;
        float inv = 1.0f / det_safe;
        bool valid = (nz > 0.0f) && (adet > EPSd);

        float a0 = (by - cy) * inv, b0 = (cx - bx) * inv;
        float c0 = -(a0 * cx + b0 * cy);
        float a1 = (cy - ay) * inv, b1 = (ax - cx) * inv;
        float c1 = -(a1 * cx + b1 * cy);

        float dz0 = valid ? (z0 - z2s) : 0.0f;
        float dz1 = valid ? (z1 - z2s) : 0.0f;
        float zc  = valid ? z2s : -1e10f;
        float fidf = valid ? (float)fg : -1.0f;

        Rr[0] = xmin; Rr[1] = xmax; Rr[2] = ymin; Rr[3] = ymax;
        Rr[4] = a0; Rr[5] = b0; Rr[6] = c0; Rr[7] = dz0;
        Rr[8] = a1; Rr[9] = b1; Rr[10] = c1; Rr[11] = dz1;
        Rr[12] = zc; Rr[13] = fidf;
        // segments (a->b), (b->c), (c->a)
        Rr[14] = ax; Rr[15] = ay;
        float v0x = bx - ax, v0y = by - ay;
        Rr[16] = v0x; Rr[17] = v0y;
        Rr[18] = 1.0f / (v0x*v0x + v0y*v0y + 1e-12f);
        Rr[19] = bx;
        Rr[20] = by;
        float v1x = cx - bx, v1y = cy - by;
        Rr[21] = v1x; Rr[22] = v1y;
        Rr[23] = 1.0f / (v1x*v1x + v1y*v1y + 1e-12f);
        Rr[24] = cx; Rr[25] = cy;
        float v2x = ax - cx, v2y = ay - cy;
        Rr[26] = v2x; Rr[27] = v2y;
        Rr[28] = 1.0f / (v2x*v2x + v2y*v2y + 1e-12f);
    }
    __syncthreads();

    // ---- pixel mapping: 16x16 tile, 8x4 per warp ----
    int lx = lane & 7, ly = lane >> 3;
    int wx = wid & 1, wy = wid >> 1;
    int x = tx * 16 + wx * 8 + lx;
    int y = ty * 16 + wy * 4 + ly;

    float px = (2.0f * (float)x + 1.0f - (float)Ww) / (float)Ww;
    float py = ((float)Hh - 2.0f * (float)y - 1.0f) / (float)Hh;

    float prod = 1.0f;
    float bestz = -1e30f;
    float bw0 = 0.0f, bw1 = 0.0f, bf = -1.0f;

    for (int f = 0; f < nf; ++f) {
        const float* Rr = &sface[f * RECF];
        float4 bb = *(const float4*)(Rr + 0);
        bool inb = (px >= bb.x) && (px <= bb.y) && (py >= bb.z) && (py <= bb.w);
        if (__ballot_sync(0xffffffffu, inb) == 0u) continue;

        float4 e0 = *(const float4*)(Rr + 4);
        float4 e1 = *(const float4*)(Rr + 8);
        float w0 = fmaf(e0.x, px, fmaf(e0.y, py, e0.z));
        float w1 = fmaf(e1.x, px, fmaf(e1.y, py, e1.z));
        float w2 = 1.0f - w0 - w1;
        bool covered = (w0 >= 0.0f) && (w1 >= 0.0f) && (w2 >= 0.0f);
        float4 zf = *(const float4*)(Rr + 12);   // zc, fid, s0px, s0py

        if (inb) {
            if (covered) {
                float z = zf.x + w0 * e0.w + w1 * e1.w;
                if (z > bestz) { bestz = z; bw0 = w0; bw1 = w1; bf = zf.y; }
                prod = 0.0f;
            } else {
                float4 s0 = *(const float4*)(Rr + 16);  // s0vx,s0vy,s0inv,s1px
                float4 s1 = *(const float4*)(Rr + 20);  // s1py,s1vx,s1vy,s1inv
                float4 s2 = *(const float4*)(Rr + 24);  // s2px,s2py,s2vx,s2vy
                float s2inv = Rr[28];

                float rx = px - zf.z, ry = py - zf.w;
                float t0 = (rx * s0.x + ry * s0.y) * s0.z;
                t0 = fminf(fmaxf(t0, 0.0f), 1.0f);
                float ex = rx - t0 * s0.x, ey = ry - t0 * s0.y;
                float d2a = ex * ex + ey * ey;

                rx = px - s0.w; ry = py - s1.x;
                float t1 = (rx * s1.y + ry * s1.z) * s1.w;
                t1 = fminf(fmaxf(t1, 0.0f), 1.0f);
                ex = rx - t1 * s1.y; ey = ry - t1 * s1.z;
                float d2b = ex * ex + ey * ey;

                rx = px - s2.x; ry = py - s2.y;
                float t2 = (rx * s2.z + ry * s2.w) * s2inv;
                t2 = fminf(fmaxf(t2, 0.0f), 1.0f);
                ex = rx - t2 * s2.z; ey = ry - t2 * s2.w;
                float d2c = ex * ex + ey * ey;

                float d2 = fminf(fminf(d2a, d2b), d2c);
                float contrib = __expf(-d2 * KEXP);
                prod *= (1.0f - contrib);
            }
        }
    }

    int pix = y * Ww + x;
    int o = (b * NCHUNK + chunk) * NPIX + pix;
    __stcg(&g_partA[o], make_float4(bestz, bw0, bw1, bf));
    __stcg(&g_partP[o], prod);

    // ---- last CTA per (b,tile) combines ----
    __threadfence();
    __syncthreads();
    if (tid == 0) sh_old = atomicAdd(&g_cnt[b * 16 + tile], 1);
    __syncthreads();
    if (sh_old != NCHUNK - 1) return;
    __threadfence();

    float Z = -1e38f, b0c = 0.0f, b1c = 0.0f, bff = -1.0f;
    float pacc = 1.0f;
    #pragma unroll
    for (int c = 0; c < NCHUNK; ++c) {
        int oo = (b * NCHUNK + c) * NPIX + pix;
        float4 a = __ldcg(&g_partA[oo]);
        pacc *= __ldcg(&g_partP[oo]);
        if (a.x > Z) { Z = a.x; b0c = a.y; b1c = a.z; bff = a.w; }
    }

    float r = 0.0f, g = 0.0f, bl = 0.0f, hm = 0.0f;
    if (bff >= 0.0f) {
        int fid = (int)bff;
        const int* fi = faces + ((size_t)(b * F + fid)) * 3;
        const float* cA = colors + ((size_t)(b * P + fi[0])) * 3;
        const float* cB = colors + ((size_t)(b * P + fi[1])) * 3;
        const float* cC = colors + ((size_t)(b * P + fi[2])) * 3;
        float w2 = 1.0f - b0c - b1c;
        r  = b0c * cA[0] + b1c * cB[0] + w2 * cC[0];
        g  = b0c * cA[1] + b1c * cB[1] + w2 * cC[1];
        bl = b0c * cA[2] + b1c * cB[2] + w2 * cC[2];
        hm = b0c + b1c + w2;
    }

    int gidx = b * NPIX + pix;
    float* rgb = out + (size_t)gidx * 3;
    rgb[0] = r; rgb[1] = g; rgb[2] = bl;
    out[offP + gidx] = 1.0f - pacc;
    out[offH + gidx] = hm;

    if (tid == 0) atomicExch(&g_cnt[b * 16 + tile], 0);   // reset for next replay
}

extern "C" void kernel_launch(void* const* d_in, const int* in_sizes, int n_in,
                              void* d_out, int out_size)
{
    const float* verts  = (const float*)d_in[0];
    const int*   faces  = (const int*)d_in[1];
    const float* rot    = (const float*)d_in[2];
    const float* pos    = (const float*)d_in[3];
    const float* proj   = (const float*)d_in[4];
    const float* colors = (const float*)d_in[5];
    float* out = (float*)d_out;

    int B = in_sizes[3] / 3;
    int P = in_sizes[0] / (3 * B);
    int F = in_sizes[1] / (3 * B);

    int offP = B * NPIX * 3;        // improb
    int offN = offP + B * NPIX;     // normal1
    int offH = offN + B * F * 3;    // hardmask

    dim3 grid(16, NCHUNK, B);
    render_kernel<<<grid, 256>>>(verts, faces, rot, pos, proj, colors, out,
                                 B, P, F, offP, offN, offH);
}